// round 16
// baseline (speedup 1.0000x reference)
#include <cuda_runtime.h>
#include <cuda_bf16.h>
#include <cstdint>

#define STEPS  30
#define HIDDEN 32
#define TPB    128
#define WARPS  (TPB / 32)          // 4
#define LPE    4                   // lanes cooperating per element-pair
#define PPW    8                   // element-pairs per warp
#define EPC    (WARPS * PPW * 2)   // 64 elements per CTA
#define UNITS  (HIDDEN / LPE)      // 8 hidden units per lane

typedef unsigned long long u64;

// ---------- packed f32x2 helpers (asm forms — proven codegen) ----------
__device__ __forceinline__ u64 pack2(float lo, float hi) {
    u64 r;
    asm("mov.b64 %0, {%1, %2};" : "=l"(r) : "f"(lo), "f"(hi));
    return r;
}
__device__ __forceinline__ void unpack2(u64 v, float& lo, float& hi) {
    asm("mov.b64 {%0, %1}, %2;" : "=f"(lo), "=f"(hi) : "l"(v));
}
__device__ __forceinline__ u64 fma2(u64 a, u64 b, u64 c) {
    u64 d;
    asm("fma.rn.f32x2 %0, %1, %2, %3;" : "=l"(d) : "l"(a), "l"(b), "l"(c));
    return d;
}
__device__ __forceinline__ u64 add2(u64 a, u64 b) {
    u64 d;
    asm("add.rn.f32x2 %0, %1, %2;" : "=l"(d) : "l"(a), "l"(b));
    return d;
}
__device__ __forceinline__ u64 relu2(u64 v) {
    float lo, hi;
    unpack2(v, lo, hi);
    lo = fmaxf(lo, 0.0f);
    hi = fmaxf(hi, 0.0f);
    return pack2(lo, hi);
}
__device__ __forceinline__ u64 shfl64_xor(u64 v, int m) {
    return __shfl_xor_sync(0xffffffffu, v, m);
}

__global__ void __launch_bounds__(TPB, 8)
rhm_kernel(const float* __restrict__ S,
           const float* __restrict__ W1,
           const float* __restrict__ b1,
           const float* __restrict__ W2,
           const float* __restrict__ b2,
           const float* __restrict__ a_init,
           float* __restrict__ out,
           int B)
{
    // sbuf2[pair][step]: .x = element 2*pair, .y = element 2*pair+1.
    __shared__ float2 sbuf2[EPC / 2][STEPS + 1];
    float* const sbufF = reinterpret_cast<float*>(sbuf2);

    const int tid  = threadIdx.x;
    const int lane = tid & 31;
    const int wid  = tid >> 5;
    const int q    = lane & (LPE - 1);             // this lane's unit-quarter
    const int pair = wid * PPW + (lane >> 2);      // pair row (0..31)

    const long long base = (long long)blockIdx.x * EPC;
    const int nvalid = (int)min((long long)EPC, (long long)B - base);
    const int ntot   = nvalid * STEPS;

    // ---- coalesced stage-in ----
    {
        const float* Sblk = S + base * STEPS;
        #pragma unroll
        for (int k = 0; k < (EPC * STEPS) / TPB; ++k) {
            int i = k * TPB + tid;
            if (i < ntot) {
                int el = i / STEPS;
                int st = i - el * STEPS;
                sbufF[(el >> 1) * (2 * (STEPS + 1)) + st * 2 + (el & 1)] = Sblk[i];
            }
        }
    }

    // ---- broadcast weight pairs; w2 pre-scaled by 0.2 (h' = 5h trick).
    //      At 64 regs ptxas will keep the hottest in registers and reload the
    //      rest from L1 (broadcast, conflict-free) — measured cheap at R15. ----
    u64 w0b[UNITS], w1b[UNITS], w2b[UNITS], b1b[UNITS], wob[UNITS];
    {
        const int ubase = q * UNITS;
        #pragma unroll
        for (int j = 0; j < UNITS; ++j) {
            int u = ubase + j;
            float a = W1[u];                    w0b[j] = pack2(a, a);
            float bb = W1[HIDDEN + u];          w1b[j] = pack2(bb, bb);
            float c = 0.2f * W1[2*HIDDEN + u];  w2b[j] = pack2(c, c);
            float dd = b1[u];                   b1b[j] = pack2(dd, dd);
            float ee = W2[u];                   wob[j] = pack2(ee, ee);
        }
    }
    const float b2s = b2[0];
    const float din = a_init[0];
    const u64 c08 = pack2(0.8f, 0.8f);
    const u64 cb2 = pack2(b2s, b2s);

    u64 h2 = 0ull;                 // h' = 5h, starts at 0
    u64 d2 = pack2(din, din);

    __syncthreads();

    // One-step-ahead s-pair prefetch (column STEPS is in-bounds padding).
    u64 s2 = *reinterpret_cast<const u64*>(&sbuf2[pair][0]);

    #pragma unroll 1
    for (int t = 0; t < STEPS; ++t) {
        u64 sn = *reinterpret_cast<const u64*>(&sbuf2[pair][t + 1]);

        u64 acc0 = 0ull, acc1 = 0ull;

        #pragma unroll
        for (int j = 0; j < UNITS; ++j) {
            u64 p = fma2(s2, w0b[j], b1b[j]);
            p = fma2(d2, w1b[j], p);
            p = fma2(h2, w2b[j], p);          // h' * (0.2 w2)
            p = relu2(p);
            if (j & 1) acc1 = fma2(p, wob[j], acc1);
            else       acc0 = fma2(p, wob[j], acc0);
        }

        u64 m2 = add2(acc0, acc1);
        m2 = add2(m2, shfl64_xor(m2, 1));
        m2 = add2(m2, shfl64_xor(m2, 2));
        u64 dn2 = add2(m2, cb2);

        h2 = fma2(h2, c08, dn2);              // h' = 0.8 h' + d
        d2 = dn2;
        if (q == 0)
            *reinterpret_cast<u64*>(&sbuf2[pair][t]) = dn2;
        s2 = sn;
    }

    __syncthreads();

    // ---- coalesced flush ----
    {
        float* Oblk = out + base * STEPS;
        #pragma unroll
        for (int k = 0; k < (EPC * STEPS) / TPB; ++k) {
            int i = k * TPB + tid;
            if (i < ntot) {
                int el = i / STEPS;
                int st = i - el * STEPS;
                Oblk[i] = sbufF[(el >> 1) * (2 * (STEPS + 1)) + st * 2 + (el & 1)];
            }
        }
    }
}

extern "C" void kernel_launch(void* const* d_in, const int* in_sizes, int n_in,
                              void* d_out, int out_size)
{
    const float* S      = (const float*)d_in[0];
    const float* W1     = (const float*)d_in[1];
    const float* b1     = (const float*)d_in[2];
    const float* W2     = (const float*)d_in[3];
    const float* b2     = (const float*)d_in[4];
    const float* a_init = (const float*)d_in[5];
    float* out = (float*)d_out;

    int B = in_sizes[0] / STEPS;
    int grid = (B + EPC - 1) / EPC;
    rhm_kernel<<<grid, TPB>>>(S, W1, b1, W2, b2, a_init, out, B);
}